// round 9
// baseline (speedup 1.0000x reference)
#include <cuda_runtime.h>
#include <cstdint>

#define MODELS 8
#define BATCH 65536
#define CHOICE 100
#define WARP_CUST 4
#define CPB 32                               // 8 warps * 4 customers
#define THREADS 256
#define NBLK (BATCH / CPB)                   // 2048
#define TILE_F4 (WARP_CUST * 25)             // 100 f4 per warp tile
#define NBUF 3
#define NTILES (2 + MODELS)                  // y, x, z0..z7
#define SMEM_BYTES (8 * NBUF * TILE_F4 * 16) // 38400
#define ZSTRIDE ((size_t)BATCH * CHOICE)

__device__ float g_partials[NBLK];
__device__ unsigned int g_count;             // zero-init; finisher resets

__device__ __forceinline__ void cp_async16(uint32_t dst_smem, const void* src) {
    asm volatile("cp.async.cg.shared.global [%0], [%1], 16;\n"
                 :: "r"(dst_smem), "l"(src));
}
__device__ __forceinline__ void cp_commit() {
    asm volatile("cp.async.commit_group;\n");
}
template <int N>
__device__ __forceinline__ void cp_wait_n() {
    asm volatile("cp.async.wait_group %0;\n" :: "n"(N));
}

extern "C" __global__ void __launch_bounds__(THREADS, 5)
mmnl_main(const float* __restrict__ x, const float* __restrict__ y,
          const float* __restrict__ z, const float* __restrict__ alpha,
          const float* __restrict__ u_prev, const float* __restrict__ u,
          float* __restrict__ out)
{
    extern __shared__ float4 sbuf[];         // 8 warps x 3 bufs x 100 f4
    const int tid  = threadIdx.x;
    const int bid  = blockIdx.x;
    const int w    = tid >> 5;
    const int lane = tid & 31;

    __shared__ float s_alpha[MODELS], s_eup[MODELS], s_wsum[8];
    __shared__ float s_eu;
    __shared__ bool  s_last;
    if (tid < MODELS) { s_alpha[tid] = alpha[tid]; s_eup[tid] = __expf(u_prev[tid]); }
    if (tid == MODELS) s_eu = __expf(u[0]);
    __syncthreads();

    float4* wbase = sbuf + w * (NBUF * TILE_F4);
    uint32_t dsts[NBUF];
#pragma unroll
    for (int b = 0; b < NBUF; b++)
        dsts[b] = (uint32_t)__cvta_generic_to_shared(wbase + b * TILE_F4)
                + (uint32_t)lane * 16u;

    const size_t cbase = (size_t)bid * CPB + (size_t)w * WARP_CUST;
    const float* ysrc = y + cbase * CHOICE;
    const float* xsrc = x + cbase * CHOICE;
    const float* zsrc = z + cbase * CHOICE;

    // contiguous 100-f4 copy: 3 full iters + 4 lanes on the 4th
    auto issue = [&](const float* src, uint32_t dst) {
        const float4* s4 = (const float4*)src + lane;
#pragma unroll
        for (int i = 0; i < 4; i++)
            if (i < 3 || lane < 4)
                cp_async16(dst + (uint32_t)(i * 512), s4 + i * 32);
        cp_commit();
    };

    const int c = lane >> 3;                 // customer within warp (0..3)
    const int o = lane & 7;                  // octant of the row
    const float mo = (o == 0) ? 1.f : 0.f;   // lane o==0 also handles f4 24

    // prime pipeline: 3 tiles in flight
    issue(ysrc, dsts[0]);
    issue(xsrc, dsts[1]);
    issue(zsrc, dsts[2]);

    bool  has = false; int c_star = 0;
    float sex = 0.f, xy = 0.f, g = 0.f;

#pragma unroll
    for (int k = 0; k < NTILES; k++) {
        const int wn = (NTILES - 1 - k) < 2 ? (NTILES - 1 - k) : 2;
        if      (wn == 2) cp_wait_n<2>();
        else if (wn == 1) cp_wait_n<1>();
        else              cp_wait_n<0>();
        __syncwarp();

        const float4* row  = wbase + (k % 3) * TILE_F4 + c * 25;
        const float*  rowf = (const float*)row;

        // lane's f4s: o, o+8, o+16; lane o==0 also 24
        if (k == 0) {
            // y: one-hot locate. comb = 1024*sum(y) + sum(y*col)
            float sy = 0.f, sl = 0.f;
#pragma unroll
            for (int s = 0; s < 3; s++) {
                float4 v = row[o + 8 * s];
                float cb = (float)(4 * o + 32 * s);
                sy += (v.x + v.y) + (v.z + v.w);
                sl  = fmaf(v.x, cb,       sl);
                sl  = fmaf(v.y, cb + 1.f, sl);
                sl  = fmaf(v.z, cb + 2.f, sl);
                sl  = fmaf(v.w, cb + 3.f, sl);
            }
            float4 v4 = row[24];             // cols 96..99
            float sy4 = (v4.x + v4.y) + (v4.z + v4.w);
            float sl4 = fmaf(v4.x, 96.f, fmaf(v4.y, 97.f,
                        fmaf(v4.z, 98.f, v4.w * 99.f)));
            sy += mo * sy4;
            sl  = fmaf(mo, sl4, sl);
            float comb = fmaf(sy, 1024.f, sl);
            comb += __shfl_xor_sync(0xffffffffu, comb, 1);
            comb += __shfl_xor_sync(0xffffffffu, comb, 2);
            comb += __shfl_xor_sync(0xffffffffu, comb, 4);
            has    = (comb > 512.f);
            c_star = has ? ((int)rintf(comb) - 1024) : 0;
        } else {
            float a0 = 0.f, a1 = 0.f;
#pragma unroll
            for (int s = 0; s < 3; s++) {
                float4 v = row[o + 8 * s];
                a0 += __expf(v.x) + __expf(v.z);
                a1 += __expf(v.y) + __expf(v.w);
            }
            float4 v4 = row[24];
            float e4  = (__expf(v4.x) + __expf(v4.z))
                      + (__expf(v4.y) + __expf(v4.w));
            float acc = a0 + a1 + mo * e4;
            acc += __shfl_xor_sync(0xffffffffu, acc, 1);
            acc += __shfl_xor_sync(0xffffffffu, acc, 2);
            acc += __shfl_xor_sync(0xffffffffu, acc, 4);
            float pick = rowf[c_star];
            if (k == 1) {
                sex = acc; xy = pick;
            } else {
                const int m = k - 2;
                float eup = s_eup[m];
                float num = has ? __expf(pick) : eup;
                g = fmaf(s_alpha[m], __fdividef(num, eup + acc), g);
            }
        }
        __syncwarp();                         // buffer k%3 free to refill

        if (k + NBUF < NTILES)
            issue(zsrc + (size_t)(k + NBUF - 2) * ZSTRIDE, dsts[k % 3]);
    }

    // per-customer term; all 8 oct lanes hold identical tval
    float eu   = s_eu;
    float numx = has ? __expf(xy) : eu;
    float tval = __fdividef(numx, (eu + sex) * g);

    float v = tval;
#pragma unroll
    for (int of = 16; of > 0; of >>= 1)
        v += __shfl_xor_sync(0xffffffffu, v, of);
    if (lane == 0) s_wsum[w] = v * 0.125f;    // octs counted 8x
    __syncthreads();

    if (w == 0) {
        float a = (lane < 8) ? s_wsum[lane] : 0.f;
#pragma unroll
        for (int of = 4; of > 0; of >>= 1)
            a += __shfl_xor_sync(0xffffffffu, a, of);
        if (lane == 0) {
            g_partials[bid] = a;
            __threadfence();
            s_last = (atomicAdd(&g_count, 1u) == (unsigned)(NBLK - 1));
        }
    }
    __syncthreads();

    if (s_last) {
        __threadfence();
        float* red = (float*)sbuf;
        float a = 0.f;
        for (int i = tid; i < NBLK; i += THREADS) a += __ldcg(&g_partials[i]);
        red[tid] = a;
        __syncthreads();
#pragma unroll
        for (int s = THREADS / 2; s > 0; s >>= 1) {
            if (tid < s) red[tid] += red[tid + s];
            __syncthreads();
        }
        if (tid == 0) {
            out[0]  = -red[0] / (float)BATCH;
            g_count = 0;                      // reset for next graph replay
        }
    }
}

extern "C" void kernel_launch(void* const* d_in, const int* in_sizes, int n_in,
                              void* d_out, int out_size)
{
    const float* x      = (const float*)d_in[0];
    const float* y      = (const float*)d_in[1];
    const float* z      = (const float*)d_in[2];
    const float* alpha  = (const float*)d_in[3];
    const float* u_prev = (const float*)d_in[4];
    const float* u      = (const float*)d_in[5];
    float* out = (float*)d_out;

    static bool attr_set = false;
    if (!attr_set) {
        cudaFuncSetAttribute(mmnl_main,
                             cudaFuncAttributeMaxDynamicSharedMemorySize,
                             SMEM_BYTES);
        attr_set = true;
    }
    mmnl_main<<<NBLK, THREADS, SMEM_BYTES>>>(x, y, z, alpha, u_prev, u, out);
}